// round 8
// baseline (speedup 1.0000x reference)
#include <cuda_runtime.h>
#include <cstdint>

// Problem shape (fixed by reference)
constexpr int B = 16, N = 8, M = 1024, F = 512;
constexpr int F4 = F / 4;              // 128 float4 columns
constexpr int M_CHUNK = 16;            // m-rows per block
constexpr int M_CHUNKS = M / M_CHUNK;  // 64
constexpr float LOG2E = 1.4426950408889634f;

__device__ __forceinline__ float ex2_approx(float x) {
    float r;
    asm("ex2.approx.f32 %0, %1;" : "=f"(r) : "f"(x));
    return r;
}
__device__ __forceinline__ float rcp_approx(float x) {
    float r;
    asm("rcp.approx.f32 %0, %1;" : "=f"(r) : "f"(x));
    return r;
}

// ---------------------------------------------------------------------------
// One block = (b, n, mc); 128 threads = one float4 f-column each. Grid 8192.
//
// Calibrated model (R3/R6/R7): DRAM% tracks in-flight rows/SM =
// warps x rotation_depth, with diminishing depth returns and a penalty for
// dropping below ~28 warps/SM. R6 (depth 2, 8 CTAs, 28 warps) = best point.
// R8: same depth-2 rotation, but 9 CTAs/SM (56-reg budget) -> 36 warps/SM,
// +12% warps at unchanged structure. Depth-2 needs only ~50 regs, so the
// cap should not distort the schedule (R3's failure mode was the cap
// destroying the batching structure, not the cap itself).
//
// Mask dtype detection in-block: values in [0,13) => int64 (LE) has every
// odd 32-bit word == 0; OR over 256 odd words nonzero for int32 w.p.
// 1-(1/13)^256.
//
// tanh(x) = 1 - 2/(exp(2x)+1)  ->  out = p - q * rcp(ex2(z*c1 + c0) + 1)
//   c1 = 2*e3*log2e, c0 = -2*e2*e3*log2e, p = e0+e1, q = 2*e1
// ---------------------------------------------------------------------------
__global__ __launch_bounds__(F4, 9)
void tanh_rt_kernel(const float4* __restrict__ z,
                    const int* __restrict__ mask32,
                    const float4* __restrict__ eta,   // [13] of (e0,e1,e2,e3)
                    float4* __restrict__ out) {
    const int f4  = threadIdx.x;           // 0..127
    const int blk = blockIdx.x;
    const int mc  = blk % M_CHUNKS;
    const int bn  = blk / M_CHUNKS;        // 0..B*N-1
    const int b   = bn / N;

    const size_t base = ((size_t)bn * M + (size_t)mc * M_CHUNK) * F4 + f4;

    // --- prefetch rows 0,1 first: overlaps the param-gather chain below ---
    float4 a0 = z[base];
    float4 a1 = z[base + F4];

    // --- in-block mask width detection (block-uniform result) ---
    unsigned acc = (unsigned)mask32[2 * f4 + 1] | (unsigned)mask32[2 * (f4 + 128) + 1];
    const int is64 = !__syncthreads_or((int)acc);

    // --- gather per-f params into registers ---
    float c1[4], c0[4], p[4], q[4];
    #pragma unroll
    for (int j = 0; j < 4; j++) {
        const int pos = b * F + f4 * 4 + j;
        const int midx = is64 ? mask32[2 * pos] : mask32[pos];
        const float4 e = __ldg(&eta[midx]);
        const float t1 = 2.0f * e.w * LOG2E;       // 2*e3*log2e
        c1[j] = t1;
        c0[j] = -e.z * t1;                         // -2*e2*e3*log2e
        p[j]  = e.x + e.y;                         // e0 + e1
        q[j]  = 2.0f * e.y;                        // 2*e1
    }

    // --- rotated loop: load next pair, then compute/store current pair ---
    #pragma unroll
    for (int m = 0; m < M_CHUNK; m += 2) {
        const float4 z0 = a0;
        const float4 z1 = a1;
        if (m + 2 < M_CHUNK) {
            a0 = z[base + (size_t)(m + 2) * F4];
            a1 = z[base + (size_t)(m + 3) * F4];
        }

        float4 o0, o1;
        o0.x = fmaf(-q[0], rcp_approx(ex2_approx(fmaf(z0.x, c1[0], c0[0])) + 1.0f), p[0]);
        o0.y = fmaf(-q[1], rcp_approx(ex2_approx(fmaf(z0.y, c1[1], c0[1])) + 1.0f), p[1]);
        o0.z = fmaf(-q[2], rcp_approx(ex2_approx(fmaf(z0.z, c1[2], c0[2])) + 1.0f), p[2]);
        o0.w = fmaf(-q[3], rcp_approx(ex2_approx(fmaf(z0.w, c1[3], c0[3])) + 1.0f), p[3]);

        o1.x = fmaf(-q[0], rcp_approx(ex2_approx(fmaf(z1.x, c1[0], c0[0])) + 1.0f), p[0]);
        o1.y = fmaf(-q[1], rcp_approx(ex2_approx(fmaf(z1.y, c1[1], c0[1])) + 1.0f), p[1]);
        o1.z = fmaf(-q[2], rcp_approx(ex2_approx(fmaf(z1.z, c1[2], c0[2])) + 1.0f), p[2]);
        o1.w = fmaf(-q[3], rcp_approx(ex2_approx(fmaf(z1.w, c1[3], c0[3])) + 1.0f), p[3]);

        out[base + (size_t)m * F4]       = o0;
        out[base + (size_t)(m + 1) * F4] = o1;
    }
}

extern "C" void kernel_launch(void* const* d_in, const int* in_sizes, int n_in,
                              void* d_out, int out_size) {
    const float4* z      = (const float4*)d_in[0];
    const int*    mask32 = (const int*)d_in[1];      // int32 or int64, detected in-kernel
    const float4* eta    = (const float4*)d_in[2];   // [13,4] fp32
    float4*       out    = (float4*)d_out;

    tanh_rt_kernel<<<B * N * M_CHUNKS, F4>>>(z, mask32, eta, out);
}

// round 9
// speedup vs baseline: 1.0190x; 1.0190x over previous
#include <cuda_runtime.h>
#include <cstdint>

// Problem shape (fixed by reference)
constexpr int B = 16, N = 8, M = 1024, F = 512;
constexpr int F4 = F / 4;              // 128 float4 columns
constexpr int M_CHUNK = 16;            // m-rows per block
constexpr int M_CHUNKS = M / M_CHUNK;  // 64
constexpr int N_FAULTS = 13;
constexpr float LOG2E = 1.4426950408889634f;

__device__ __forceinline__ float ex2_approx(float x) {
    float r;
    asm("ex2.approx.f32 %0, %1;" : "=f"(r) : "f"(x));
    return r;
}
__device__ __forceinline__ float rcp_approx(float x) {
    float r;
    asm("rcp.approx.f32 %0, %1;" : "=f"(r) : "f"(x));
    return r;
}

// ---------------------------------------------------------------------------
// One block = (b, n, mc); 128 threads = one float4 f-column each. Grid 8192.
// R6 config (depth-2 rotation, 8 CTAs/SM) — measured optimum of the
// warps x depth surface over R3/R6/R7/R8.
//
// R9: collapse the prologue's 3 dependent L2 trips to 1 so it hides fully
// under the initial z prefetch:
//  - speculative dual-width mask loads (both int32/int64 candidates) issued
//    in parallel with the detection loads; select in registers after the OR.
//  - eta[13] staged to shared memory concurrently; the __syncthreads_or
//    barrier doubles as the smem fence; gather becomes a ~29-cyc LDS.
//
// Mask dtype detection: values in [0,13) => int64 (LE) has every odd 32-bit
// word == 0; OR over 256 odd words nonzero for int32 w.p. 1-(1/13)^256.
//
// tanh(x) = 1 - 2/(exp(2x)+1)  ->  out = p - q * rcp(ex2(z*c1 + c0) + 1)
//   c1 = 2*e3*log2e, c0 = -2*e2*e3*log2e, p = e0+e1, q = 2*e1
// ---------------------------------------------------------------------------
__global__ __launch_bounds__(F4, 8)
void tanh_rt_kernel(const float4* __restrict__ z,
                    const int* __restrict__ mask32,
                    const float4* __restrict__ eta,   // [13] of (e0,e1,e2,e3)
                    float4* __restrict__ out) {
    __shared__ float4 s_eta[N_FAULTS];

    const int f4  = threadIdx.x;           // 0..127
    const int blk = blockIdx.x;
    const int mc  = blk % M_CHUNKS;
    const int bn  = blk / M_CHUNKS;        // 0..B*N-1
    const int b   = bn / N;

    const size_t base = ((size_t)bn * M + (size_t)mc * M_CHUNK) * F4 + f4;

    // --- (1) prefetch z rows 0,1 (DRAM, covers everything below) ---
    float4 a0 = z[base];
    float4 a1 = z[base + F4];

    // --- (2) speculative mask loads, both widths, all 4 f-lanes (parallel) ---
    int m32v[4], m64v[4];
    #pragma unroll
    for (int j = 0; j < 4; j++) {
        const int pos = b * F + f4 * 4 + j;
        m32v[j] = mask32[pos];
        m64v[j] = mask32[2 * pos];
    }

    // --- (3) eta -> smem (13 threads, parallel with the above) ---
    if (f4 < N_FAULTS) s_eta[f4] = eta[f4];

    // --- (4) detection loads (parallel) + block OR; bar fences smem too ---
    unsigned acc = (unsigned)mask32[2 * f4 + 1] | (unsigned)mask32[2 * (f4 + 128) + 1];
    const int is64 = !__syncthreads_or((int)acc);

    // --- (5) register select + LDS gather + param math ---
    float c1[4], c0[4], p[4], q[4];
    #pragma unroll
    for (int j = 0; j < 4; j++) {
        const int midx = is64 ? m64v[j] : m32v[j];
        const float4 e = s_eta[midx];
        const float t1 = 2.0f * e.w * LOG2E;       // 2*e3*log2e
        c1[j] = t1;
        c0[j] = -e.z * t1;                         // -2*e2*e3*log2e
        p[j]  = e.x + e.y;                         // e0 + e1
        q[j]  = 2.0f * e.y;                        // 2*e1
    }

    // --- rotated loop: load next pair, then compute/store current pair ---
    #pragma unroll
    for (int m = 0; m < M_CHUNK; m += 2) {
        const float4 z0 = a0;
        const float4 z1 = a1;
        if (m + 2 < M_CHUNK) {
            a0 = z[base + (size_t)(m + 2) * F4];
            a1 = z[base + (size_t)(m + 3) * F4];
        }

        float4 o0, o1;
        o0.x = fmaf(-q[0], rcp_approx(ex2_approx(fmaf(z0.x, c1[0], c0[0])) + 1.0f), p[0]);
        o0.y = fmaf(-q[1], rcp_approx(ex2_approx(fmaf(z0.y, c1[1], c0[1])) + 1.0f), p[1]);
        o0.z = fmaf(-q[2], rcp_approx(ex2_approx(fmaf(z0.z, c1[2], c0[2])) + 1.0f), p[2]);
        o0.w = fmaf(-q[3], rcp_approx(ex2_approx(fmaf(z0.w, c1[3], c0[3])) + 1.0f), p[3]);

        o1.x = fmaf(-q[0], rcp_approx(ex2_approx(fmaf(z1.x, c1[0], c0[0])) + 1.0f), p[0]);
        o1.y = fmaf(-q[1], rcp_approx(ex2_approx(fmaf(z1.y, c1[1], c0[1])) + 1.0f), p[1]);
        o1.z = fmaf(-q[2], rcp_approx(ex2_approx(fmaf(z1.z, c1[2], c0[2])) + 1.0f), p[2]);
        o1.w = fmaf(-q[3], rcp_approx(ex2_approx(fmaf(z1.w, c1[3], c0[3])) + 1.0f), p[3]);

        out[base + (size_t)m * F4]       = o0;
        out[base + (size_t)(m + 1) * F4] = o1;
    }
}

extern "C" void kernel_launch(void* const* d_in, const int* in_sizes, int n_in,
                              void* d_out, int out_size) {
    const float4* z      = (const float4*)d_in[0];
    const int*    mask32 = (const int*)d_in[1];      // int32 or int64, detected in-kernel
    const float4* eta    = (const float4*)d_in[2];   // [13,4] fp32
    float4*       out    = (float4*)d_out;

    tanh_rt_kernel<<<B * N * M_CHUNKS, F4>>>(z, mask32, eta, out);
}

// round 10
// speedup vs baseline: 1.0194x; 1.0004x over previous
#include <cuda_runtime.h>
#include <cstdint>

// Problem shape (fixed by reference)
constexpr int B = 16, N = 8, M = 1024, F = 512;
constexpr int F4 = F / 4;              // 128 float4 columns
constexpr int M_CHUNK = 32;            // m-rows per block (2 rows in parallel)
constexpr int M_CHUNKS = M / M_CHUNK;  // 32
constexpr int THREADS = 256;           // half*128 + f4
constexpr int N_FAULTS = 13;
constexpr float LOG2E = 1.4426950408889634f;

__device__ __forceinline__ float ex2_approx(float x) {
    float r;
    asm("ex2.approx.f32 %0, %1;" : "=f"(r) : "f"(x));
    return r;
}
__device__ __forceinline__ float rcp_approx(float x) {
    float r;
    asm("rcp.approx.f32 %0, %1;" : "=f"(r) : "f"(x));
    return r;
}

// ---------------------------------------------------------------------------
// One block = (b, n, mc) covering 32 m-rows with 256 threads: lane f4 = t&127
// picks the float4 f-column, half = t>>7 picks odd/even rows. Per-thread
// structure identical to the R9 optimum (depth-2 rotated stream over 16 rows,
// prologue hidden under the first z prefetch), but block count halves
// (8192 -> 4096) so prologue issue, detection L2 traffic, and rotation tail
// drains all halve. Concurrency also halves (4 CTAs x 256 thr @ 64 regs =
// full RF), so wave count (6.92) and 92%-full tail wave are preserved.
//
// Mask dtype detection: values in [0,13) => int64 (LE) has every odd 32-bit
// word == 0; OR over 256 odd words nonzero for int32 w.p. 1-(1/13)^256.
// Speculative dual-width mask loads + eta staged to smem keep the prologue
// to a single dependent L2 trip.
//
// tanh(x) = 1 - 2/(exp(2x)+1)  ->  out = p - q * rcp(ex2(z*c1 + c0) + 1)
//   c1 = 2*e3*log2e, c0 = -2*e2*e3*log2e, p = e0+e1, q = 2*e1
// ---------------------------------------------------------------------------
__global__ __launch_bounds__(THREADS, 4)
void tanh_rt_kernel(const float4* __restrict__ z,
                    const int* __restrict__ mask32,
                    const float4* __restrict__ eta,   // [13] of (e0,e1,e2,e3)
                    float4* __restrict__ out) {
    __shared__ float4 s_eta[N_FAULTS];

    const int tid  = threadIdx.x;
    const int f4   = tid & 127;            // 0..127: float4 f-column
    const int half = tid >> 7;             // 0/1: even/odd rows
    const int blk  = blockIdx.x;
    const int mc   = blk % M_CHUNKS;
    const int bn   = blk / M_CHUNKS;       // 0..B*N-1
    const int b    = bn / N;

    // thread's first row: mc*32 + half; row stride = 2
    const size_t base = ((size_t)bn * M + (size_t)mc * M_CHUNK + half) * F4 + f4;
    const size_t RS = 2 * F4;              // row stride in float4

    // --- (1) prefetch this thread's rows 0,1 (DRAM; covers prologue) ---
    float4 a0 = z[base];
    float4 a1 = z[base + RS];

    // --- (2) speculative mask loads, both widths, all 4 f-lanes ---
    int m32v[4], m64v[4];
    #pragma unroll
    for (int j = 0; j < 4; j++) {
        const int pos = b * F + f4 * 4 + j;
        m32v[j] = mask32[pos];
        m64v[j] = mask32[2 * pos];
    }

    // --- (3) eta -> smem (13 threads, parallel) ---
    if (tid < N_FAULTS) s_eta[tid] = eta[tid];

    // --- (4) detection: 256 threads, 1 odd word each; bar fences smem ---
    unsigned acc = (unsigned)mask32[2 * tid + 1];
    const int is64 = !__syncthreads_or((int)acc);

    // --- (5) register select + LDS gather + param math ---
    float c1[4], c0[4], p[4], q[4];
    #pragma unroll
    for (int j = 0; j < 4; j++) {
        const int midx = is64 ? m64v[j] : m32v[j];
        const float4 e = s_eta[midx];
        const float t1 = 2.0f * e.w * LOG2E;       // 2*e3*log2e
        c1[j] = t1;
        c0[j] = -e.z * t1;                         // -2*e2*e3*log2e
        p[j]  = e.x + e.y;                         // e0 + e1
        q[j]  = 2.0f * e.y;                        // 2*e1
    }

    // --- rotated loop over this thread's 16 rows (stride-2 in m) ---
    #pragma unroll
    for (int i = 0; i < 16; i += 2) {
        const float4 z0 = a0;
        const float4 z1 = a1;
        if (i + 2 < 16) {
            a0 = z[base + (size_t)(i + 2) * RS];
            a1 = z[base + (size_t)(i + 3) * RS];
        }

        float4 o0, o1;
        o0.x = fmaf(-q[0], rcp_approx(ex2_approx(fmaf(z0.x, c1[0], c0[0])) + 1.0f), p[0]);
        o0.y = fmaf(-q[1], rcp_approx(ex2_approx(fmaf(z0.y, c1[1], c0[1])) + 1.0f), p[1]);
        o0.z = fmaf(-q[2], rcp_approx(ex2_approx(fmaf(z0.z, c1[2], c0[2])) + 1.0f), p[2]);
        o0.w = fmaf(-q[3], rcp_approx(ex2_approx(fmaf(z0.w, c1[3], c0[3])) + 1.0f), p[3]);

        o1.x = fmaf(-q[0], rcp_approx(ex2_approx(fmaf(z1.x, c1[0], c0[0])) + 1.0f), p[0]);
        o1.y = fmaf(-q[1], rcp_approx(ex2_approx(fmaf(z1.y, c1[1], c0[1])) + 1.0f), p[1]);
        o1.z = fmaf(-q[2], rcp_approx(ex2_approx(fmaf(z1.z, c1[2], c0[2])) + 1.0f), p[2]);
        o1.w = fmaf(-q[3], rcp_approx(ex2_approx(fmaf(z1.w, c1[3], c0[3])) + 1.0f), p[3]);

        out[base + (size_t)i * RS]       = o0;
        out[base + (size_t)(i + 1) * RS] = o1;
    }
}

extern "C" void kernel_launch(void* const* d_in, const int* in_sizes, int n_in,
                              void* d_out, int out_size) {
    const float4* z      = (const float4*)d_in[0];
    const int*    mask32 = (const int*)d_in[1];      // int32 or int64, detected in-kernel
    const float4* eta    = (const float4*)d_in[2];   // [13,4] fp32
    float4*       out    = (float4*)d_out;

    tanh_rt_kernel<<<B * N * M_CHUNKS, THREADS>>>(z, mask32, eta, out);
}